// round 8
// baseline (speedup 1.0000x reference)
#include <cuda_runtime.h>
#include <cuda_bf16.h>
#include <cstdint>

// PARAFAC / CP reconstruction: out[a,b,c] = sum_k f0[k,a]*f1[k,b]*f2[k,c]
// A=B=C=512, RANK=16, fp32 out (536 MB stores).
//
// Round-8: mma.sync.m16n8k16 bf16 (sm_80+ ISA, legal on base sm_100 unlike tcgen05).
// Split-bf16 K=48: A(g)=[hi|lo|hi], B(f2)=[hi|hi|lo] -> Ah*Bh + Al*Bh + Ah*Bl,
// dropped term ~2^-16 -> rel_err ~1e-5 (threshold 1e-3).
//   M=b, N=c. D-frag: thread holds c-pair at rows t/4, t/4+8 -> STG.64, 128B/wf.
//   B-frag: F2 split tile in SMEM, [c][k] rows, PITCH=112B (28-bank stride ->
//           conflict-free for the (t/4 row, t%4 lane) LDS.32 pattern).
//   A-frag: g computed directly into fragment registers (8 vals/thread/warp-tile).
// Removes the 64us fp32-FMA busy-floor that pinned rounds 2-5 at 96us.

#define A_DIM 512
#define B_DIM 512
#define C_DIM 512
#define RANK  16
#define BTILE 64       // b per block = 4 warps x 16 rows
#define CTILE 128      // c per block = 16 n-blocks x 8
#define NTHREADS 128
#define PITCH 112      // bytes per c-row in F2s (hi[16] @0, lo[16] @32)

__device__ __forceinline__ uint32_t bfpack(__nv_bfloat16 e0, __nv_bfloat16 e1) {
    __nv_bfloat162 p;
    p.x = e0;  // low 16 bits = first (even-k) element
    p.y = e1;
    return *reinterpret_cast<uint32_t*>(&p);
}

__device__ __forceinline__ void split_bf16(float v, __nv_bfloat16& hi, __nv_bfloat16& lo) {
    hi = __float2bfloat16(v);
    lo = __float2bfloat16(v - __bfloat162float(hi));
}

__device__ __forceinline__ void mma16816(float& d0, float& d1, float& d2, float& d3,
                                         uint32_t a0, uint32_t a1, uint32_t a2, uint32_t a3,
                                         uint32_t b0, uint32_t b1) {
    asm volatile(
        "mma.sync.aligned.m16n8k16.row.col.f32.bf16.bf16.f32 "
        "{%0,%1,%2,%3}, {%4,%5,%6,%7}, {%8,%9}, {%0,%1,%2,%3};"
        : "+f"(d0), "+f"(d1), "+f"(d2), "+f"(d3)
        : "r"(a0), "r"(a1), "r"(a2), "r"(a3), "r"(b0), "r"(b1));
}

__global__ __launch_bounds__(NTHREADS, 6)
void parafac_mma_kernel(const float* __restrict__ f0,
                        const float* __restrict__ f1,
                        const float* __restrict__ f2,
                        float* __restrict__ out)
{
    // F2 split tile: row c (0..127), bytes [0,32)=hi[k0..15], [32,64)=lo[k0..15]
    __shared__ __align__(16) unsigned char F2s[CTILE * PITCH];   // 14336 B

    const int a  = blockIdx.z;
    const int b0 = blockIdx.y * BTILE;
    const int c0 = blockIdx.x * CTILE;
    const int t  = threadIdx.x;
    const int w    = t >> 5;
    const int lane = t & 31;
    const int q    = lane & 3;   // thread-in-group
    const int r    = lane >> 2;  // group id (row / col selector)

    // ---- stage F2 split tile: 128 c x 16 k, coalesced over c ----
    for (int i = t; i < CTILE * RANK; i += NTHREADS) {
        int k  = i >> 7;        // 0..15
        int cc = i & 127;       // 0..127 (contiguous per k -> coalesced LDG)
        float v = f2[k * C_DIM + c0 + cc];
        __nv_bfloat16 hi, lo;
        split_bf16(v, hi, lo);
        unsigned char* row = F2s + cc * PITCH;
        *reinterpret_cast<__nv_bfloat16*>(row + k * 2)      = hi;
        *reinterpret_cast<__nv_bfloat16*>(row + 32 + k * 2) = lo;
    }

    // ---- A fragments (g side), computed directly per documented m16n8k16 coords ----
    // a0: (row r,   k 2q,2q+1)  a1: (row r+8, same)  a2: (row r, k 2q+8,+9)  a3: (row r+8, same)
    const int br0 = b0 + w * 16 + r;
    const int br1 = br0 + 8;
    uint32_t ah[4], al[4];
    {
        const int ks[2] = { 2 * q, 2 * q + 8 };
#pragma unroll
        for (int h = 0; h < 2; h++) {
            int k0 = ks[h], k1 = ks[h] + 1;
            float ga0 = f0[k0 * A_DIM + a] * f1[k0 * B_DIM + br0];
            float ga1 = f0[k1 * A_DIM + a] * f1[k1 * B_DIM + br0];
            float gb0 = f0[k0 * A_DIM + a] * f1[k0 * B_DIM + br1];
            float gb1 = f0[k1 * A_DIM + a] * f1[k1 * B_DIM + br1];
            __nv_bfloat16 h0, l0, h1, l1;
            split_bf16(ga0, h0, l0); split_bf16(ga1, h1, l1);
            ah[2 * h + 0] = bfpack(h0, h1);
            al[2 * h + 0] = bfpack(l0, l1);
            split_bf16(gb0, h0, l0); split_bf16(gb1, h1, l1);
            ah[2 * h + 1] = bfpack(h0, h1);
            al[2 * h + 1] = bfpack(l0, l1);
        }
    }
    __syncthreads();

    // ---- loop over 16 n-blocks of 8 c ----
    // B-frag coords: b0 = B[k 2q,2q+1][col r], b1 = B[k 2q+8,+9][col r]
    //   -> in F2s[c][k]: LDS.32 at row (8m + r), byte 4q (hi) / 32+4q (lo); +16 for k+8.
    float* obase = out + (size_t)a * (B_DIM * C_DIM) + (size_t)c0;

#pragma unroll 4
    for (int m = 0; m < CTILE / 8; m++) {
        const unsigned char* row = F2s + (8 * m + r) * PITCH + 4 * q;
        uint32_t bh0 = *reinterpret_cast<const uint32_t*>(row);
        uint32_t bh1 = *reinterpret_cast<const uint32_t*>(row + 16);
        uint32_t bl0 = *reinterpret_cast<const uint32_t*>(row + 32);
        uint32_t bl1 = *reinterpret_cast<const uint32_t*>(row + 48);

        float d0 = 0.f, d1 = 0.f, d2 = 0.f, d3 = 0.f;
        mma16816(d0, d1, d2, d3, ah[0], ah[1], ah[2], ah[3], bh0, bh1); // Ah*Bh
        mma16816(d0, d1, d2, d3, al[0], al[1], al[2], al[3], bh0, bh1); // Al*Bh
        mma16816(d0, d1, d2, d3, ah[0], ah[1], ah[2], ah[3], bl0, bl1); // Ah*Bl

        // D-frag: d0,d1 = D[r][2q,2q+1] ; d2,d3 = D[r+8][2q,2q+1]
        const int c = 8 * m + 2 * q;
        *reinterpret_cast<float2*>(obase + (size_t)br0 * C_DIM + c) = make_float2(d0, d1);
        *reinterpret_cast<float2*>(obase + (size_t)br1 * C_DIM + c) = make_float2(d2, d3);
    }
}

extern "C" void kernel_launch(void* const* d_in, const int* in_sizes, int n_in,
                              void* d_out, int out_size)
{
    const float* f0 = (const float*)d_in[0];
    const float* f1 = (const float*)d_in[1];
    const float* f2 = (const float*)d_in[2];
    float* out = (float*)d_out;

    dim3 grid(C_DIM / CTILE, B_DIM / BTILE, A_DIM);   // (4, 8, 512) = 16384 blocks
    dim3 block(NTHREADS);
    parafac_mma_kernel<<<grid, block>>>(f0, f1, f2, out);
}